// round 16
// baseline (speedup 1.0000x reference)
#include <cuda_runtime.h>
#include <cuda_fp16.h>
#include <cstdint>

// Problem constants
#define BATCH   4
#define SEQ     2048
#define CDIM    1024
#define NHEAD   16
#define DHEAD   64
#define MROWS   (BATCH * SEQ)          // 8192
#define BH      (BATCH * NHEAD)        // 64

// Scratch (device globals; no allocations allowed)
__device__ __half g_q[(size_t)BH * SEQ * DHEAD];   // [BH][T][D], q pre-scaled by 0.125*log2e
__device__ __half g_k[(size_t)BH * SEQ * DHEAD];
__device__ __half g_v[(size_t)BH * SEQ * DHEAD];
__device__ __half g_xh[(size_t)MROWS * CDIM];      // x, fp16
__device__ __half g_yh[(size_t)MROWS * CDIM];      // attn out, fp16 [B,T,C]
__device__ __half g_wt1[(size_t)3072 * 1024];      // w_attn^T, fp16
__device__ __half g_wt2[(size_t)1024 * 1024];      // w_proj^T, fp16

// ---------------------------------------------------------------------------
// Helpers
// ---------------------------------------------------------------------------
__device__ __forceinline__ uint32_t smem_u32(const void* p) {
    uint32_t a;
    asm("{ .reg .u64 t; cvta.to.shared.u64 t, %1; cvt.u32.u64 %0, t; }" : "=r"(a) : "l"(p));
    return a;
}
__device__ __forceinline__ void cp16(uint32_t smem_dst, const void* gsrc) {
    asm volatile("cp.async.cg.shared.global [%0], [%1], 16;" :: "r"(smem_dst), "l"(gsrc));
}
#define CP_COMMIT() asm volatile("cp.async.commit_group;" ::: "memory")
#define CP_WAIT(N)  asm volatile("cp.async.wait_group %0;" :: "n"(N) : "memory")

// m16n8k16 fp16 MMA (row.col), fp32 accumulate
__device__ __forceinline__ void mma_f16(float c[4], const uint32_t a[4],
                                        uint32_t b0, uint32_t b1) {
    asm volatile(
        "mma.sync.aligned.m16n8k16.row.col.f32.f16.f16.f32 "
        "{%0,%1,%2,%3}, {%4,%5,%6,%7}, {%8,%9}, {%0,%1,%2,%3};\n"
        : "+f"(c[0]), "+f"(c[1]), "+f"(c[2]), "+f"(c[3])
        : "r"(a[0]), "r"(a[1]), "r"(a[2]), "r"(a[3]), "r"(b0), "r"(b1));
}

// ldmatrix x4 (b16), non-transposed / transposed
__device__ __forceinline__ void ldsm4(uint32_t& r0, uint32_t& r1,
                                      uint32_t& r2, uint32_t& r3, uint32_t addr) {
    asm volatile("ldmatrix.sync.aligned.m8n8.x4.shared.b16 {%0,%1,%2,%3}, [%4];"
                 : "=r"(r0), "=r"(r1), "=r"(r2), "=r"(r3) : "r"(addr));
}
__device__ __forceinline__ void ldsm4t(uint32_t& r0, uint32_t& r1,
                                       uint32_t& r2, uint32_t& r3, uint32_t addr) {
    asm volatile("ldmatrix.sync.aligned.m8n8.x4.trans.shared.b16 {%0,%1,%2,%3}, [%4];"
                 : "=r"(r0), "=r"(r1), "=r"(r2), "=r"(r3) : "r"(addr));
}

__device__ __forceinline__ uint32_t h2_u32(float a, float b) {
    __half2 h = __floats2half2_rn(a, b);
    return *(uint32_t*)&h;
}

// ---------------------------------------------------------------------------
// Merged pre-pass: one launch covering
//   job 0: x  fp32->fp16          (8192 blocks)
//   job 1: w_attn transpose+cvt   (96*32 = 3072 blocks)
//   job 2: w_proj transpose+cvt   (32*32 = 1024 blocks)
// ---------------------------------------------------------------------------
#define PRE_BLOCKS (8192 + 3072 + 1024)

__global__ __launch_bounds__(256)
void prepass(const float* __restrict__ x,
             const float* __restrict__ w_attn,
             const float* __restrict__ w_proj,
             __half* __restrict__ xh,
             __half* __restrict__ wt1,
             __half* __restrict__ wt2)
{
    const int blk = blockIdx.x;
    const int tid = threadIdx.x;

    if (blk < 8192) {
        int i = blk * 256 + tid;
        float4 v = ((const float4*)x)[i];
        uint2 o;
        o.x = h2_u32(v.x, v.y);
        o.y = h2_u32(v.z, v.w);
        ((uint2*)xh)[i] = o;
        return;
    }

    __shared__ float tile[32][33];
    const float* W;
    __half* WT;
    int N, bx, by;
    if (blk < 8192 + 3072) {
        int idx = blk - 8192;
        W = w_attn; WT = wt1; N = 3072;
        bx = idx % 96; by = idx / 96;
    } else {
        int idx = blk - 8192 - 3072;
        W = w_proj; WT = wt2; N = 1024;
        bx = idx % 32; by = idx / 32;
    }
    int n0 = bx * 32;
    int k0 = by * 32;
    int tx = tid & 31, ty = tid >> 5;    // 32 x 8
#pragma unroll
    for (int i = ty; i < 32; i += 8)
        tile[i][tx] = W[(size_t)(k0 + i) * N + n0 + tx];
    __syncthreads();
#pragma unroll
    for (int i = ty; i < 32; i += 8)
        WT[(size_t)(n0 + i) * 1024 + k0 + tx] = __float2half(tile[tx][i]);
}

// ---------------------------------------------------------------------------
// fp16 mma.sync GEMM: 128x128 CTA tile, 4 warps of 64x64, BK=32,
// 4-stage cp.async pipeline (CP_WAIT(2): two slabs always in flight),
// one __syncthreads per slab. Scalar LDS.32 fragment loads (pitch 40).
// ---------------------------------------------------------------------------
#define PH 40
#define STG_H (128 * PH)                          // halves per matrix
#define GEMM_SMEM (4 * 2 * STG_H * 2)             // 81,920 B

template <bool SCATTER>
__global__ __launch_bounds__(128)
void gemm_mma(const __half* __restrict__ A, const __half* __restrict__ BT,
              const float* __restrict__ bias, float* __restrict__ out)
{
    extern __shared__ __half smh[];

    const int tid = threadIdx.x;
    const int wid = tid >> 5;
    const int lane = tid & 31;
    const int wr = wid >> 1;
    const int wc = wid & 1;
    const int c0 = blockIdx.x * 128;
    const int r0 = blockIdx.y * 128;

    const __half* Ab = A + (size_t)r0 * 1024;
    const __half* Bb = BT + (size_t)c0 * 1024;

    float acc[4][8][4];
#pragma unroll
    for (int mt = 0; mt < 4; mt++)
#pragma unroll
        for (int nt = 0; nt < 8; nt++)
#pragma unroll
            for (int u = 0; u < 4; u++) acc[mt][nt][u] = 0.f;

    auto stage = [&](int c, int st) {
        __half* sA = smh + st * 2 * STG_H;
        __half* sB = sA + STG_H;
        const int k0 = c * 32;
#pragma unroll
        for (int i = 0; i < 4; i++) {
            int slot = tid + i * 128;        // 0..511
            int row = slot >> 2;             // 0..127
            int kq = (slot & 3) * 8;         // 0,8,16,24 halves
            cp16(smem_u32(&sA[row * PH + kq]),
                 Ab + (size_t)row * 1024 + k0 + kq);
            cp16(smem_u32(&sB[row * PH + kq]),
                 Bb + (size_t)row * 1024 + k0 + kq);
        }
        CP_COMMIT();
    };

    stage(0, 0);
    stage(1, 1);
    stage(2, 2);

    const int lr = lane >> 2;
    const int lk = lane & 3;

    for (int c = 0; c < 32; c++) {
        const int st = c & 3;
        CP_WAIT(2);                  // slab c resident (c+1, c+2 may be in flight)
        __syncthreads();             // visibility + everyone done with stage st
        if (c + 3 < 32) stage(c + 3, (c + 3) & 3);
        else CP_COMMIT();            // keep group accounting aligned

        const __half* tA = smh + st * 2 * STG_H + wr * 64 * PH;
        const __half* tB = smh + st * 2 * STG_H + STG_H + wc * 64 * PH;
#pragma unroll
        for (int ks = 0; ks < 2; ks++) {
            uint32_t b[8][2];
#pragma unroll
            for (int nt = 0; nt < 8; nt++) {
                const __half* Bn = &tB[(nt * 8 + lr) * PH + ks * 16 + 2 * lk];
                b[nt][0] = *(const uint32_t*)Bn;
                b[nt][1] = *(const uint32_t*)(Bn + 8);
            }
#pragma unroll
            for (int mt = 0; mt < 4; mt++) {
                const __half* Am = &tA[(mt * 16 + lr) * PH + ks * 16 + 2 * lk];
                uint32_t a[4];
                a[0] = *(const uint32_t*)Am;
                a[1] = *(const uint32_t*)(Am + 8 * PH);
                a[2] = *(const uint32_t*)(Am + 8);
                a[3] = *(const uint32_t*)(Am + 8 * PH + 8);
#pragma unroll
                for (int nt = 0; nt < 8; nt++)
                    mma_f16(acc[mt][nt], a, b[nt][0], b[nt][1]);
            }
        }
    }

    const int lc = (lane & 3) * 2;
#pragma unroll
    for (int mt = 0; mt < 4; mt++) {
#pragma unroll
        for (int nt = 0; nt < 8; nt++) {
            int m = r0 + wr * 64 + mt * 16 + lr;
            int n = c0 + wc * 64 + nt * 8 + lc;
            float b0 = bias[n], b1 = bias[n + 1];
            float v00 = acc[mt][nt][0] + b0, v01 = acc[mt][nt][1] + b1;
            float v10 = acc[mt][nt][2] + b0, v11 = acc[mt][nt][3] + b1;
            if (SCATTER) {
                int which = n >> 10;
                int cc = n & 1023;
                int h = cc >> 6;
                int d = cc & 63;
                int bb = m >> 11;
                int t = m & 2047;
                if (which == 0) {
                    const float qs = 0.125f * 1.44269504089f;   // 1/sqrt(D)*log2e
                    v00 *= qs; v01 *= qs; v10 *= qs; v11 *= qs;
                }
                __half* dst = (which == 0) ? g_q : (which == 1) ? g_k : g_v;
                size_t base = (size_t)(bb * NHEAD + h) * SEQ;
                *(uint32_t*)(dst + (base + t) * DHEAD + d) = h2_u32(v00, v01);
                *(uint32_t*)(dst + (base + t + 8) * DHEAD + d) = h2_u32(v10, v11);
            } else {
                *(float2*)(out + (size_t)m * 1024 + n) = make_float2(v00, v01);
                *(float2*)(out + (size_t)(m + 8) * 1024 + n) = make_float2(v10, v11);
            }
        }
    }
}

// ---------------------------------------------------------------------------
// fp16 tensor-core flash attention (m16n8k16, fp32 softmax/accum, exp2 domain)
// grid (16, 64), 8 warps x 16 Q rows. K/V natural [s][d] (pitch 72 halves).
// S accumulators repacked directly into PV A-fragments.
// Warp-uniform causal skipping: S-tile pair j covers cols k0+16j..+15,
// PV k-step ks covers cols k0+16ks..+15 (16 cols each!).
// ---------------------------------------------------------------------------
#define PHK 72
#define KBUFH (64 * PHK)
#define SMEM_ATTN (6 * KBUFH * 2)                 // 55,296 B

__global__ __launch_bounds__(256)
void attn_mma()
{
    extern __shared__ __half smah[];
    __half* sK[3] = {smah, smah + KBUFH, smah + 2 * KBUFH};
    __half* sV[3] = {smah + 3 * KBUFH, smah + 4 * KBUFH, smah + 5 * KBUFH};

    const int qi = (int)gridDim.x - 1 - (int)blockIdx.x;   // heavy tiles first
    const int bh = blockIdx.y;
    const int tid = threadIdx.x;
    const int wid = tid >> 5;
    const int lane = tid & 31;
    const int lr = lane >> 2;        // 0..7
    const int lk = lane & 3;         // 0..3
    const int lg = lane >> 3;        // ldmatrix matrix idx
    const int lrow = lane & 7;       // ldmatrix row
    const int warp_m = wid * 16;
    const int q0 = qi * 128;

    const __half* Kg = g_k + (size_t)bh * SEQ * DHEAD;
    const __half* Vg = g_v + (size_t)bh * SEQ * DHEAD;

    auto stage = [&](int kt, int b) {
        const int k0 = kt * 64;
#pragma unroll
        for (int i = 0; i < 2; i++) {
            int slot = tid + i * 256;        // 0..511
            int row = slot >> 3;             // 0..63
            int cq = (slot & 7) * 8;         // 0..56 halves
            cp16(smem_u32(&sK[b][row * PHK + cq]), Kg + (size_t)(k0 + row) * 64 + cq);
            cp16(smem_u32(&sV[b][row * PHK + cq]), Vg + (size_t)(k0 + row) * 64 + cq);
        }
        CP_COMMIT();
    };

    // Q fragments (pre-scaled by 0.125*log2e at QKV epilogue): 4 k-steps of 16
    uint32_t qf[4][4];
    {
        const __half* Qw = g_q + ((size_t)bh * SEQ + q0 + warp_m) * DHEAD;
#pragma unroll
        for (int ks = 0; ks < 4; ks++) {
            const __half* p = Qw + lr * 64 + ks * 16 + 2 * lk;
            qf[ks][0] = *(const uint32_t*)p;
            qf[ks][1] = *(const uint32_t*)(p + 8 * 64);
            qf[ks][2] = *(const uint32_t*)(p + 8);
            qf[ks][3] = *(const uint32_t*)(p + 8 * 64 + 8);
        }
    }

    float o[8][4];
#pragma unroll
    for (int nt = 0; nt < 8; nt++)
#pragma unroll
        for (int u = 0; u < 4; u++) o[nt][u] = 0.f;

    float m0 = -1e30f, m1 = -1e30f, l0 = 0.f, l1 = 0.f;
    const int row0 = q0 + warp_m + lr;
    const int row1 = row0 + 8;
    const int lim = q0 + warp_m + 15;     // warp's last owned row

    const int nkt = (qi + 1) * 2;
    stage(0, 0);
    if (nkt > 1) stage(1, 1); else CP_COMMIT();

    for (int kt = 0; kt < nkt; kt++) {
        const int st = kt % 3;
        const int k0 = kt * 64;

        CP_WAIT(1);                  // tile kt resident (kt+1 pending)
        __syncthreads();             // visibility; all warps finished kt-1
        if (kt + 2 < nkt) stage(kt + 2, (kt + 2) % 3);
        else CP_COMMIT();

        if (k0 > lim) continue;      // warp fully above diagonal

        const __half* cK = sK[st];
        const __half* cV = sV[st];

        // S = Q K^T (16 x 64 per warp), fp32 accum (log2 domain).
        // nt-pair j covers columns [k0+16j, k0+16j+15]; skip if past lim.
        float s[8][4];
#pragma unroll
        for (int nt = 0; nt < 8; nt++)
#pragma unroll
            for (int u = 0; u < 4; u++) s[nt][u] = -1e30f;

#pragma unroll
        for (int j = 0; j < 4; j++) {
            if (k0 + 16 * j > lim) break;      // warp-uniform
#pragma unroll
            for (int u = 0; u < 4; u++) {
                s[2 * j][u] = 0.f;
                s[2 * j + 1][u] = 0.f;
            }
#pragma unroll
            for (int ks = 0; ks < 4; ks++) {
                uint32_t b0, b1, b2, b3;
                int n = (2 * j + (lg >> 1)) * 8 + lrow;
                int k = ks * 16 + (lg & 1) * 8;
                ldsm4(b0, b1, b2, b3, smem_u32(&cK[n * PHK + k]));
                mma_f16(s[2 * j], qf[ks], b0, b1);
                mma_f16(s[2 * j + 1], qf[ks], b2, b3);
            }
        }

        // Causal mask (element-level) + row max
        const bool need_mask = (k0 + 63 > row0);
        float rmax0 = -1e30f, rmax1 = -1e30f;
#pragma unroll
        for (int nt = 0; nt < 8; nt++) {
            if (need_mask) {
                const int cb = k0 + nt * 8 + 2 * lk;
                if (cb     > row0) s[nt][0] = -1e30f;
                if (cb + 1 > row0) s[nt][1] = -1e30f;
                if (cb     > row1) s[nt][2] = -1e30f;
                if (cb + 1 > row1) s[nt][3] = -1e30f;
            }
            rmax0 = fmaxf(rmax0, fmaxf(s[nt][0], s[nt][1]));
            rmax1 = fmaxf(rmax1, fmaxf(s[nt][2], s[nt][3]));
        }
        rmax0 = fmaxf(rmax0, __shfl_xor_sync(0xffffffffu, rmax0, 1));
        rmax0 = fmaxf(rmax0, __shfl_xor_sync(0xffffffffu, rmax0, 2));
        rmax1 = fmaxf(rmax1, __shfl_xor_sync(0xffffffffu, rmax1, 1));
        rmax1 = fmaxf(rmax1, __shfl_xor_sync(0xffffffffu, rmax1, 2));

        const float mn0 = fmaxf(m0, rmax0);
        const float mn1 = fmaxf(m1, rmax1);
        const float a0 = exp2f(m0 - mn0);
        const float a1 = exp2f(m1 - mn1);
        m0 = mn0; m1 = mn1;

        float rs0 = 0.f, rs1 = 0.f;
#pragma unroll
        for (int nt = 0; nt < 8; nt++) {
            s[nt][0] = exp2f(s[nt][0] - mn0);
            s[nt][1] = exp2f(s[nt][1] - mn0);
            s[nt][2] = exp2f(s[nt][2] - mn1);
            s[nt][3] = exp2f(s[nt][3] - mn1);
            rs0 += s[nt][0] + s[nt][1];
            rs1 += s[nt][2] + s[nt][3];
        }
        rs0 += __shfl_xor_sync(0xffffffffu, rs0, 1);
        rs0 += __shfl_xor_sync(0xffffffffu, rs0, 2);
        rs1 += __shfl_xor_sync(0xffffffffu, rs1, 1);
        rs1 += __shfl_xor_sync(0xffffffffu, rs1, 2);
        l0 = l0 * a0 + rs0;
        l1 = l1 * a1 + rs1;

#pragma unroll
        for (int nt = 0; nt < 8; nt++) {
            o[nt][0] *= a0; o[nt][1] *= a0;
            o[nt][2] *= a1; o[nt][3] *= a1;
        }

        // O += P @ V; k-step ks covers S-columns [k0+16ks, k0+16ks+15]
        // -> skip only when the step's FIRST column is already past lim.
        const int sm_row = lane & 15;
        const int sm_col = (lane >> 4) * 8;
#pragma unroll
        for (int ks = 0; ks < 4; ks++) {
            if (k0 + 16 * ks > lim) break;     // warp-uniform (P == 0 there)
            uint32_t ap[4];
            ap[0] = h2_u32(s[2 * ks][0],     s[2 * ks][1]);
            ap[1] = h2_u32(s[2 * ks][2],     s[2 * ks][3]);
            ap[2] = h2_u32(s[2 * ks + 1][0], s[2 * ks + 1][1]);
            ap[3] = h2_u32(s[2 * ks + 1][2], s[2 * ks + 1][3]);
#pragma unroll
            for (int ntp = 0; ntp < 4; ntp++) {
                uint32_t r0, r1, r2, r3;
                ldsm4t(r0, r1, r2, r3,
                       smem_u32(&cV[(ks * 16 + sm_row) * PHK + ntp * 16 + sm_col]));
                mma_f16(o[2 * ntp],     ap, r0, r1);
                mma_f16(o[2 * ntp + 1], ap, r2, r3);
            }
        }
    }

    // Epilogue: normalize, write y as fp16 [B,T,C]
    const float inv0 = 1.f / l0;
    const float inv1 = 1.f / l1;
    const int b = bh >> 4;
    const int h = bh & 15;
    __half* y0 = g_yh + ((size_t)(b * SEQ + row0)) * CDIM + h * 64;
    __half* y1 = g_yh + ((size_t)(b * SEQ + row1)) * CDIM + h * 64;
#pragma unroll
    for (int nt = 0; nt < 8; nt++) {
        int d = nt * 8 + 2 * lk;
        *(uint32_t*)(y0 + d) = h2_u32(o[nt][0] * inv0, o[nt][1] * inv0);
        *(uint32_t*)(y1 + d) = h2_u32(o[nt][2] * inv1, o[nt][3] * inv1);
    }
}

// ---------------------------------------------------------------------------
extern "C" void kernel_launch(void* const* d_in, const int* in_sizes, int n_in,
                              void* d_out, int out_size)
{
    const float* x      = (const float*)d_in[0];
    const float* w_attn = (const float*)d_in[1];
    const float* b_attn = (const float*)d_in[2];
    const float* w_proj = (const float*)d_in[3];
    const float* b_proj = (const float*)d_in[4];
    float* out = (float*)d_out;

    cudaFuncSetAttribute(attn_mma, cudaFuncAttributeMaxDynamicSharedMemorySize,
                         SMEM_ATTN);
    cudaFuncSetAttribute(gemm_mma<true>, cudaFuncAttributeMaxDynamicSharedMemorySize,
                         GEMM_SMEM);
    cudaFuncSetAttribute(gemm_mma<false>, cudaFuncAttributeMaxDynamicSharedMemorySize,
                         GEMM_SMEM);

    void* xh_ptr = nullptr;  cudaGetSymbolAddress(&xh_ptr, g_xh);
    void* yh_ptr = nullptr;  cudaGetSymbolAddress(&yh_ptr, g_yh);
    void* wt1_ptr = nullptr; cudaGetSymbolAddress(&wt1_ptr, g_wt1);
    void* wt2_ptr = nullptr; cudaGetSymbolAddress(&wt2_ptr, g_wt2);

    // 0) merged pre-pass: x fp16 + both weight transposes, one launch
    prepass<<<PRE_BLOCKS, 256>>>(x, w_attn, w_proj,
                                 (__half*)xh_ptr, (__half*)wt1_ptr, (__half*)wt2_ptr);

    // 1) QKV projection (fp16 mma) + scatter to [BH][T][D] (q scaled)
    gemm_mma<true><<<dim3(3072 / 128, MROWS / 128), 128, GEMM_SMEM>>>(
        (const __half*)xh_ptr, (const __half*)wt1_ptr, b_attn, nullptr);

    // 2) Causal flash attention (fp16 mma, exp2 domain)
    attn_mma<<<dim3(SEQ / 128, BH), 256, SMEM_ATTN>>>();

    // 3) Output projection (fp16 mma)
    gemm_mma<false><<<dim3(1024 / 128, MROWS / 128), 128, GEMM_SMEM>>>(
        (const __half*)yh_ptr, (const __half*)wt2_ptr, b_proj, out);
}

// round 17
// speedup vs baseline: 1.1161x; 1.1161x over previous
#include <cuda_runtime.h>
#include <cuda_fp16.h>
#include <cstdint>

// Problem constants
#define BATCH   4
#define SEQ     2048
#define CDIM    1024
#define NHEAD   16
#define DHEAD   64
#define MROWS   (BATCH * SEQ)          // 8192
#define BH      (BATCH * NHEAD)        // 64

// Scratch (device globals; no allocations allowed)
__device__ __half g_q[(size_t)BH * SEQ * DHEAD];   // [BH][T][D], q pre-scaled by 0.125*log2e
__device__ __half g_k[(size_t)BH * SEQ * DHEAD];
__device__ __half g_v[(size_t)BH * SEQ * DHEAD];
__device__ __half g_xh[(size_t)MROWS * CDIM];      // x, fp16
__device__ __half g_yh[(size_t)MROWS * CDIM];      // attn out, fp16 [B,T,C]
__device__ __half g_wt1[(size_t)3072 * 1024];      // w_attn^T, fp16
__device__ __half g_wt2[(size_t)1024 * 1024];      // w_proj^T, fp16

// ---------------------------------------------------------------------------
// Helpers
// ---------------------------------------------------------------------------
__device__ __forceinline__ uint32_t smem_u32(const void* p) {
    uint32_t a;
    asm("{ .reg .u64 t; cvta.to.shared.u64 t, %1; cvt.u32.u64 %0, t; }" : "=r"(a) : "l"(p));
    return a;
}
__device__ __forceinline__ void cp16(uint32_t smem_dst, const void* gsrc) {
    asm volatile("cp.async.cg.shared.global [%0], [%1], 16;" :: "r"(smem_dst), "l"(gsrc));
}
#define CP_COMMIT() asm volatile("cp.async.commit_group;" ::: "memory")
#define CP_WAIT(N)  asm volatile("cp.async.wait_group %0;" :: "n"(N) : "memory")

// m16n8k16 fp16 MMA (row.col), fp32 accumulate
__device__ __forceinline__ void mma_f16(float c[4], const uint32_t a[4],
                                        uint32_t b0, uint32_t b1) {
    asm volatile(
        "mma.sync.aligned.m16n8k16.row.col.f32.f16.f16.f32 "
        "{%0,%1,%2,%3}, {%4,%5,%6,%7}, {%8,%9}, {%0,%1,%2,%3};\n"
        : "+f"(c[0]), "+f"(c[1]), "+f"(c[2]), "+f"(c[3])
        : "r"(a[0]), "r"(a[1]), "r"(a[2]), "r"(a[3]), "r"(b0), "r"(b1));
}

// ldmatrix x4 (b16), non-transposed / transposed
__device__ __forceinline__ void ldsm4(uint32_t& r0, uint32_t& r1,
                                      uint32_t& r2, uint32_t& r3, uint32_t addr) {
    asm volatile("ldmatrix.sync.aligned.m8n8.x4.shared.b16 {%0,%1,%2,%3}, [%4];"
                 : "=r"(r0), "=r"(r1), "=r"(r2), "=r"(r3) : "r"(addr));
}
__device__ __forceinline__ void ldsm4t(uint32_t& r0, uint32_t& r1,
                                       uint32_t& r2, uint32_t& r3, uint32_t addr) {
    asm volatile("ldmatrix.sync.aligned.m8n8.x4.trans.shared.b16 {%0,%1,%2,%3}, [%4];"
                 : "=r"(r0), "=r"(r1), "=r"(r2), "=r"(r3) : "r"(addr));
}

__device__ __forceinline__ uint32_t h2_u32(float a, float b) {
    __half2 h = __floats2half2_rn(a, b);
    return *(uint32_t*)&h;
}

// ---------------------------------------------------------------------------
// Merged pre-pass: one launch covering
//   job 0: x  fp32->fp16          (8192 blocks)
//   job 1: w_attn transpose+cvt   (96*32 = 3072 blocks)
//   job 2: w_proj transpose+cvt   (32*32 = 1024 blocks)
// ---------------------------------------------------------------------------
#define PRE_BLOCKS (8192 + 3072 + 1024)

__global__ __launch_bounds__(256)
void prepass(const float* __restrict__ x,
             const float* __restrict__ w_attn,
             const float* __restrict__ w_proj,
             __half* __restrict__ xh,
             __half* __restrict__ wt1,
             __half* __restrict__ wt2)
{
    const int blk = blockIdx.x;
    const int tid = threadIdx.x;

    if (blk < 8192) {
        int i = blk * 256 + tid;
        float4 v = ((const float4*)x)[i];
        uint2 o;
        o.x = h2_u32(v.x, v.y);
        o.y = h2_u32(v.z, v.w);
        ((uint2*)xh)[i] = o;
        return;
    }

    __shared__ float tile[32][33];
    const float* W;
    __half* WT;
    int N, bx, by;
    if (blk < 8192 + 3072) {
        int idx = blk - 8192;
        W = w_attn; WT = wt1; N = 3072;
        bx = idx % 96; by = idx / 96;
    } else {
        int idx = blk - 8192 - 3072;
        W = w_proj; WT = wt2; N = 1024;
        bx = idx % 32; by = idx / 32;
    }
    int n0 = bx * 32;
    int k0 = by * 32;
    int tx = tid & 31, ty = tid >> 5;    // 32 x 8
#pragma unroll
    for (int i = ty; i < 32; i += 8)
        tile[i][tx] = W[(size_t)(k0 + i) * N + n0 + tx];
    __syncthreads();
#pragma unroll
    for (int i = ty; i < 32; i += 8)
        WT[(size_t)(n0 + i) * 1024 + k0 + tx] = __float2half(tile[tx][i]);
}

// ---------------------------------------------------------------------------
// fp16 mma.sync GEMM (exact R14/R13/R11 config — best measured):
// 128x128 CTA tile, 4 warps of 64x64 output each, BK=32 (2 k-steps of 16),
// 3-stage cp.async pipeline, one __syncthreads per slab.
// Scalar LDS.32 fragment loads (pitch 40 halves = 80B rows, conflict-free).
// ---------------------------------------------------------------------------
#define PH 40
#define STG_H (128 * PH)                          // halves per matrix
#define GEMM_SMEM (3 * 2 * STG_H * 2)             // 61,440 B

template <bool SCATTER>
__global__ __launch_bounds__(128)
void gemm_mma(const __half* __restrict__ A, const __half* __restrict__ BT,
              const float* __restrict__ bias, float* __restrict__ out)
{
    extern __shared__ __half smh[];

    const int tid = threadIdx.x;
    const int wid = tid >> 5;
    const int lane = tid & 31;
    const int wr = wid >> 1;
    const int wc = wid & 1;
    const int c0 = blockIdx.x * 128;
    const int r0 = blockIdx.y * 128;

    const __half* Ab = A + (size_t)r0 * 1024;
    const __half* Bb = BT + (size_t)c0 * 1024;

    float acc[4][8][4];
#pragma unroll
    for (int mt = 0; mt < 4; mt++)
#pragma unroll
        for (int nt = 0; nt < 8; nt++)
#pragma unroll
            for (int u = 0; u < 4; u++) acc[mt][nt][u] = 0.f;

    auto stage = [&](int c, int st) {
        __half* sA = smh + st * 2 * STG_H;
        __half* sB = sA + STG_H;
        const int k0 = c * 32;
#pragma unroll
        for (int i = 0; i < 4; i++) {
            int slot = tid + i * 128;        // 0..511
            int row = slot >> 2;             // 0..127
            int kq = (slot & 3) * 8;         // 0,8,16,24 halves
            cp16(smem_u32(&sA[row * PH + kq]),
                 Ab + (size_t)row * 1024 + k0 + kq);
            cp16(smem_u32(&sB[row * PH + kq]),
                 Bb + (size_t)row * 1024 + k0 + kq);
        }
        CP_COMMIT();
    };

    stage(0, 0);
    stage(1, 1);

    const int lr = lane >> 2;
    const int lk = lane & 3;

    for (int c = 0; c < 32; c++) {
        const int st = c % 3;
        CP_WAIT(1);
        __syncthreads();
        if (c + 2 < 32) stage(c + 2, (c + 2) % 3);
        else CP_COMMIT();

        const __half* tA = smh + st * 2 * STG_H + wr * 64 * PH;
        const __half* tB = smh + st * 2 * STG_H + STG_H + wc * 64 * PH;
#pragma unroll
        for (int ks = 0; ks < 2; ks++) {
            uint32_t b[8][2];
#pragma unroll
            for (int nt = 0; nt < 8; nt++) {
                const __half* Bn = &tB[(nt * 8 + lr) * PH + ks * 16 + 2 * lk];
                b[nt][0] = *(const uint32_t*)Bn;
                b[nt][1] = *(const uint32_t*)(Bn + 8);
            }
#pragma unroll
            for (int mt = 0; mt < 4; mt++) {
                const __half* Am = &tA[(mt * 16 + lr) * PH + ks * 16 + 2 * lk];
                uint32_t a[4];
                a[0] = *(const uint32_t*)Am;
                a[1] = *(const uint32_t*)(Am + 8 * PH);
                a[2] = *(const uint32_t*)(Am + 8);
                a[3] = *(const uint32_t*)(Am + 8 * PH + 8);
#pragma unroll
                for (int nt = 0; nt < 8; nt++)
                    mma_f16(acc[mt][nt], a, b[nt][0], b[nt][1]);
            }
        }
    }

    const int lc = (lane & 3) * 2;
#pragma unroll
    for (int mt = 0; mt < 4; mt++) {
#pragma unroll
        for (int nt = 0; nt < 8; nt++) {
            int m = r0 + wr * 64 + mt * 16 + lr;
            int n = c0 + wc * 64 + nt * 8 + lc;
            float b0 = bias[n], b1 = bias[n + 1];
            float v00 = acc[mt][nt][0] + b0, v01 = acc[mt][nt][1] + b1;
            float v10 = acc[mt][nt][2] + b0, v11 = acc[mt][nt][3] + b1;
            if (SCATTER) {
                int which = n >> 10;
                int cc = n & 1023;
                int h = cc >> 6;
                int d = cc & 63;
                int bb = m >> 11;
                int t = m & 2047;
                if (which == 0) {
                    const float qs = 0.125f * 1.44269504089f;   // 1/sqrt(D)*log2e
                    v00 *= qs; v01 *= qs; v10 *= qs; v11 *= qs;
                }
                __half* dst = (which == 0) ? g_q : (which == 1) ? g_k : g_v;
                size_t base = (size_t)(bb * NHEAD + h) * SEQ;
                *(uint32_t*)(dst + (base + t) * DHEAD + d) = h2_u32(v00, v01);
                *(uint32_t*)(dst + (base + t + 8) * DHEAD + d) = h2_u32(v10, v11);
            } else {
                *(float2*)(out + (size_t)m * 1024 + n) = make_float2(v00, v01);
                *(float2*)(out + (size_t)(m + 8) * 1024 + n) = make_float2(v10, v11);
            }
        }
    }
}

// ---------------------------------------------------------------------------
// fp16 tensor-core flash attention (R14 structure + verified causal skips)
// m16n8k16, fp32 softmax/accum, exp2 domain. grid (16, 64), 8 warps x 16 Q rows.
// K/V natural [s][d] (pitch 72 halves). S accumulators repacked directly into
// PV A-fragments. 3-buffer cp.async, one barrier per tile.
// Warp-uniform skips: S-tile pair j and PV k-step ks each cover 16 columns.
// ---------------------------------------------------------------------------
#define PHK 72
#define KBUFH (64 * PHK)
#define SMEM_ATTN (6 * KBUFH * 2)                 // 55,296 B

__global__ __launch_bounds__(256)
void attn_mma()
{
    extern __shared__ __half smah[];
    __half* sK[3] = {smah, smah + KBUFH, smah + 2 * KBUFH};
    __half* sV[3] = {smah + 3 * KBUFH, smah + 4 * KBUFH, smah + 5 * KBUFH};

    const int qi = (int)gridDim.x - 1 - (int)blockIdx.x;   // heavy tiles first
    const int bh = blockIdx.y;
    const int tid = threadIdx.x;
    const int wid = tid >> 5;
    const int lane = tid & 31;
    const int lr = lane >> 2;        // 0..7
    const int lk = lane & 3;         // 0..3
    const int lg = lane >> 3;        // ldmatrix matrix idx
    const int lrow = lane & 7;       // ldmatrix row
    const int warp_m = wid * 16;
    const int q0 = qi * 128;

    const __half* Kg = g_k + (size_t)bh * SEQ * DHEAD;
    const __half* Vg = g_v + (size_t)bh * SEQ * DHEAD;

    auto stage = [&](int kt, int b) {
        const int k0 = kt * 64;
#pragma unroll
        for (int i = 0; i < 2; i++) {
            int slot = tid + i * 256;        // 0..511
            int row = slot >> 3;             // 0..63
            int cq = (slot & 7) * 8;         // 0..56 halves
            cp16(smem_u32(&sK[b][row * PHK + cq]), Kg + (size_t)(k0 + row) * 64 + cq);
            cp16(smem_u32(&sV[b][row * PHK + cq]), Vg + (size_t)(k0 + row) * 64 + cq);
        }
        CP_COMMIT();
    };

    // Q fragments (pre-scaled by 0.125*log2e at QKV epilogue): 4 k-steps of 16
    uint32_t qf[4][4];
    {
        const __half* Qw = g_q + ((size_t)bh * SEQ + q0 + warp_m) * DHEAD;
#pragma unroll
        for (int ks = 0; ks < 4; ks++) {
            const __half* p = Qw + lr * 64 + ks * 16 + 2 * lk;
            qf[ks][0] = *(const uint32_t*)p;
            qf[ks][1] = *(const uint32_t*)(p + 8 * 64);
            qf[ks][2] = *(const uint32_t*)(p + 8);
            qf[ks][3] = *(const uint32_t*)(p + 8 * 64 + 8);
        }
    }

    float o[8][4];
#pragma unroll
    for (int nt = 0; nt < 8; nt++)
#pragma unroll
        for (int u = 0; u < 4; u++) o[nt][u] = 0.f;

    float m0 = -1e30f, m1 = -1e30f, l0 = 0.f, l1 = 0.f;
    const int row0 = q0 + warp_m + lr;
    const int row1 = row0 + 8;
    const int lim = q0 + warp_m + 15;     // warp's last owned row

    const int nkt = (qi + 1) * 2;
    stage(0, 0);
    if (nkt > 1) stage(1, 1); else CP_COMMIT();

    for (int kt = 0; kt < nkt; kt++) {
        const int st = kt % 3;
        const int k0 = kt * 64;

        CP_WAIT(1);                  // tile kt resident (kt+1 pending)
        __syncthreads();             // visibility; all warps finished kt-1
        if (kt + 2 < nkt) stage(kt + 2, (kt + 2) % 3);
        else CP_COMMIT();

        if (k0 > lim) continue;      // warp fully above diagonal

        const __half* cK = sK[st];
        const __half* cV = sV[st];

        // S = Q K^T (16 x 64 per warp), fp32 accum (log2 domain).
        // nt-pair j covers columns [k0+16j, k0+16j+15]; skip if past lim.
        float s[8][4];
#pragma unroll
        for (int nt = 0; nt < 8; nt++)
#pragma unroll
            for (int u = 0; u < 4; u++) s[nt][u] = -1e30f;

#pragma unroll
        for (int j = 0; j < 4; j++) {
            if (k0 + 16 * j > lim) break;      // warp-uniform
#pragma unroll
            for (int u = 0; u < 4; u++) {
                s[2 * j][u] = 0.f;
                s[2 * j + 1][u] = 0.f;
            }
#pragma unroll
            for (int ks = 0; ks < 4; ks++) {
                uint32_t b0, b1, b2, b3;
                int n = (2 * j + (lg >> 1)) * 8 + lrow;
                int k = ks * 16 + (lg & 1) * 8;
                ldsm4(b0, b1, b2, b3, smem_u32(&cK[n * PHK + k]));
                mma_f16(s[2 * j], qf[ks], b0, b1);
                mma_f16(s[2 * j + 1], qf[ks], b2, b3);
            }
        }

        // Causal mask (element-level) + row max
        const bool need_mask = (k0 + 63 > row0);
        float rmax0 = -1e30f, rmax1 = -1e30f;
#pragma unroll
        for (int nt = 0; nt < 8; nt++) {
            if (need_mask) {
                const int cb = k0 + nt * 8 + 2 * lk;
                if (cb     > row0) s[nt][0] = -1e30f;
                if (cb + 1 > row0) s[nt][1] = -1e30f;
                if (cb     > row1) s[nt][2] = -1e30f;
                if (cb + 1 > row1) s[nt][3] = -1e30f;
            }
            rmax0 = fmaxf(rmax0, fmaxf(s[nt][0], s[nt][1]));
            rmax1 = fmaxf(rmax1, fmaxf(s[nt][2], s[nt][3]));
        }
        rmax0 = fmaxf(rmax0, __shfl_xor_sync(0xffffffffu, rmax0, 1));
        rmax0 = fmaxf(rmax0, __shfl_xor_sync(0xffffffffu, rmax0, 2));
        rmax1 = fmaxf(rmax1, __shfl_xor_sync(0xffffffffu, rmax1, 1));
        rmax1 = fmaxf(rmax1, __shfl_xor_sync(0xffffffffu, rmax1, 2));

        const float mn0 = fmaxf(m0, rmax0);
        const float mn1 = fmaxf(m1, rmax1);
        const float a0 = exp2f(m0 - mn0);
        const float a1 = exp2f(m1 - mn1);
        m0 = mn0; m1 = mn1;

        float rs0 = 0.f, rs1 = 0.f;
#pragma unroll
        for (int nt = 0; nt < 8; nt++) {
            s[nt][0] = exp2f(s[nt][0] - mn0);
            s[nt][1] = exp2f(s[nt][1] - mn0);
            s[nt][2] = exp2f(s[nt][2] - mn1);
            s[nt][3] = exp2f(s[nt][3] - mn1);
            rs0 += s[nt][0] + s[nt][1];
            rs1 += s[nt][2] + s[nt][3];
        }
        rs0 += __shfl_xor_sync(0xffffffffu, rs0, 1);
        rs0 += __shfl_xor_sync(0xffffffffu, rs0, 2);
        rs1 += __shfl_xor_sync(0xffffffffu, rs1, 1);
        rs1 += __shfl_xor_sync(0xffffffffu, rs1, 2);
        l0 = l0 * a0 + rs0;
        l1 = l1 * a1 + rs1;

#pragma unroll
        for (int nt = 0; nt < 8; nt++) {
            o[nt][0] *= a0; o[nt][1] *= a0;
            o[nt][2] *= a1; o[nt][3] *= a1;
        }

        // O += P @ V; k-step ks covers S-columns [k0+16ks, k0+16ks+15]
        const int sm_row = lane & 15;
        const int sm_col = (lane >> 4) * 8;
#pragma unroll
        for (int ks = 0; ks < 4; ks++) {
            if (k0 + 16 * ks > lim) break;     // warp-uniform (P == 0 there)
            uint32_t ap[4];
            ap[0] = h2_u32(s[2 * ks][0],     s[2 * ks][1]);
            ap[1] = h2_u32(s[2 * ks][2],     s[2 * ks][3]);
            ap[2] = h2_u32(s[2 * ks + 1][0], s[2 * ks + 1][1]);
            ap[3] = h2_u32(s[2 * ks + 1][2], s[2 * ks + 1][3]);
#pragma unroll
            for (int ntp = 0; ntp < 4; ntp++) {
                uint32_t r0, r1, r2, r3;
                ldsm4t(r0, r1, r2, r3,
                       smem_u32(&cV[(ks * 16 + sm_row) * PHK + ntp * 16 + sm_col]));
                mma_f16(o[2 * ntp],     ap, r0, r1);
                mma_f16(o[2 * ntp + 1], ap, r2, r3);
            }
        }
    }

    // Epilogue: normalize, write y as fp16 [B,T,C]
    const float inv0 = 1.f / l0;
    const float inv1 = 1.f / l1;
    const int b = bh >> 4;
    const int h = bh & 15;
    __half* y0 = g_yh + ((size_t)(b * SEQ + row0)) * CDIM + h * 64;
    __half* y1 = g_yh + ((size_t)(b * SEQ + row1)) * CDIM + h * 64;
#pragma unroll
    for (int nt = 0; nt < 8; nt++) {
        int d = nt * 8 + 2 * lk;
        *(uint32_t*)(y0 + d) = h2_u32(o[nt][0] * inv0, o[nt][1] * inv0);
        *(uint32_t*)(y1 + d) = h2_u32(o[nt][2] * inv1, o[nt][3] * inv1);
    }
}

// ---------------------------------------------------------------------------
extern "C" void kernel_launch(void* const* d_in, const int* in_sizes, int n_in,
                              void* d_out, int out_size)
{
    const float* x      = (const float*)d_in[0];
    const float* w_attn = (const float*)d_in[1];
    const float* b_attn = (const float*)d_in[2];
    const float* w_proj = (const float*)d_in[3];
    const float* b_proj = (const float*)d_in[4];
    float* out = (float*)d_out;

    cudaFuncSetAttribute(attn_mma, cudaFuncAttributeMaxDynamicSharedMemorySize,
                         SMEM_ATTN);
    cudaFuncSetAttribute(gemm_mma<true>, cudaFuncAttributeMaxDynamicSharedMemorySize,
                         GEMM_SMEM);
    cudaFuncSetAttribute(gemm_mma<false>, cudaFuncAttributeMaxDynamicSharedMemorySize,
                         GEMM_SMEM);

    void* xh_ptr = nullptr;  cudaGetSymbolAddress(&xh_ptr, g_xh);
    void* yh_ptr = nullptr;  cudaGetSymbolAddress(&yh_ptr, g_yh);
    void* wt1_ptr = nullptr; cudaGetSymbolAddress(&wt1_ptr, g_wt1);
    void* wt2_ptr = nullptr; cudaGetSymbolAddress(&wt2_ptr, g_wt2);

    // 0) merged pre-pass: x fp16 + both weight transposes, one launch
    prepass<<<PRE_BLOCKS, 256>>>(x, w_attn, w_proj,
                                 (__half*)xh_ptr, (__half*)wt1_ptr, (__half*)wt2_ptr);

    // 1) QKV projection (fp16 mma) + scatter to [BH][T][D] (q scaled)
    gemm_mma<true><<<dim3(3072 / 128, MROWS / 128), 128, GEMM_SMEM>>>(
        (const __half*)xh_ptr, (const __half*)wt1_ptr, b_attn, nullptr);

    // 2) Causal flash attention (fp16 mma, exp2 domain, causal skips)
    attn_mma<<<dim3(SEQ / 128, BH), 256, SMEM_ATTN>>>();

    // 3) Output projection (fp16 mma)
    gemm_mma<false><<<dim3(1024 / 128, MROWS / 128), 128, GEMM_SMEM>>>(
        (const __half*)yh_ptr, (const __half*)wt2_ptr, b_proj, out);
}